// round 14
// baseline (speedup 1.0000x reference)
#include <cuda_runtime.h>
#include <cstdint>

// Batched Thomas tridiagonal solve, B=2048, N=8192, chunked via diagonal
// dominance (alpha in [0,0.3)). Continuant (D/S) recurrence, rcp.approx
// off the dependence chain.
// R13 = R12's proven structure (L=128, HF=8, HB=16, rolled tiles, smem
// checkpoints, regs~89) with TPB 128->64: smem/block drops 88.7->44.7KB so
// 5 blocks/SM fit = 10 warps/SM (+25% occupancy) with NO register-cap or
// code-bloat side effects (the traps of R6/R7/R11).

#define N_COLSK 8192
#define L_OWN   128
#define HF      8
#define HB      16
#define SPAN_C  153                 // HF + 128 + 16 + 1; odd pitch -> conflict-free LDS
#define TPB     64
#define NTILES  9                   // 9 x 16 steps over the 144 post-halo cols

#define SM_F    (TPB * SPAN_C)                      // f slice
#define SM_CK   (SM_F + SPAN_C + 3)                 // checkpoints (cp then dp)
#define CKOFF   (NTILES * TPB)
#define SM_DUMP (SM_CK + 2 * NTILES * TPB)          // dump slots for masked lanes
#define SMEM_FLOATS (SM_DUMP + TPB)
#define SMEM_BYTES  (SMEM_FLOATS * 4)               // 44,656 B -> 5 blocks/SM

__device__ __forceinline__ float frcp(float x) {
    float r; asm("rcp.approx.f32 %0, %1;" : "=f"(r) : "f"(x)); return r;
}

// cp.async 4B; src_sz = 0 zero-fills the destination (OOB handling).
__device__ __forceinline__ void cpa4(unsigned int saddr, const float* g, int src_sz) {
    asm volatile("cp.async.ca.shared.global [%0], [%1], 4, %2;"
                 :: "r"(saddr), "l"(g), "r"(src_sz));
}

__global__ __launch_bounds__(TPB, 5)
void thomas_chunk_kernel(const float* __restrict__ alpha,
                         const float* __restrict__ f,
                         float* __restrict__ out)
{
    extern __shared__ float smem[];
    float* fS  = smem + SM_F;
    float* ckS = smem + SM_CK;

    const int tid  = threadIdx.x;
    const int cc   = blockIdx.x;                 // chunk column (0..63)
    const int row0 = blockIdx.y * TPB;
    const int s    = cc * L_OWN;
    const int col0 = s - HF;                     // first staged col (>= -8)

    // ================= cp.async staging (3 cols/lane, 64 rows) ==============
    {
        const unsigned int smb  = (unsigned int)__cvta_generic_to_shared(smem);
        const unsigned int dump = smb + (unsigned int)(SM_DUMP + tid) * 4u;

        const int c1 = col0 + tid;                       // col tid
        const int c2 = col0 + TPB + tid;                 // col tid+64
        const int c3 = col0 + 2 * TPB + tid;             // col tid+128 (tid<25)
        const int sz1 = (c1 >= 0 && c1 < N_COLSK) ? 4 : 0;
        const int sz2 = (c2 < N_COLSK) ? 4 : 0;          // c2 >= 56 always
        const bool l3 = (tid < SPAN_C - 2 * TPB);        // 25 lanes
        const int sz3 = (l3 && c3 < N_COLSK) ? 4 : 0;
        const int c1c = max(0, min(c1, N_COLSK - 1));
        const int c2c = min(c2, N_COLSK - 1);
        const int c3c = min(c3, N_COLSK - 1);

        const float* g1 = alpha + (size_t)row0 * N_COLSK + c1c;
        const float* g2 = alpha + (size_t)row0 * N_COLSK + c2c;
        const float* g3 = alpha + (size_t)row0 * N_COLSK + c3c;
        unsigned int s1 = smb + (unsigned int)tid * 4u;
        unsigned int s2 = smb + (unsigned int)(TPB + tid) * 4u;
        unsigned int s3 = l3 ? (smb + (unsigned int)(2 * TPB + tid) * 4u) : dump;
        const unsigned int step3 = l3 ? (SPAN_C * 4u) : 0u;

        #pragma unroll 4
        for (int r = 0; r < TPB; ++r) {
            cpa4(s1, g1, sz1);
            cpa4(s2, g2, sz2);
            cpa4(s3, g3, sz3);
            s1 += SPAN_C * 4u;
            s2 += SPAN_C * 4u;
            s3 += step3;
            g1 += N_COLSK; g2 += N_COLSK; g3 += N_COLSK;
        }
        // f slice (broadcast rhs)
        const unsigned int fsb = smb + SM_F * 4u;
        cpa4(fsb + (unsigned int)tid * 4u, f + c1c, sz1);
        cpa4(fsb + (unsigned int)(TPB + tid) * 4u, f + c2c, sz2);
        cpa4(l3 ? (fsb + (unsigned int)(2 * TPB + tid) * 4u) : dump, f + c3c, sz3);

        asm volatile("cp.async.commit_group;");
        asm volatile("cp.async.wait_group 0;");
    }
    __syncthreads();

    const float* sA = smem + tid * SPAN_C;

    // ================= phase 1: forward continuant sweep =================
    float Dmm = 0.0f, Dm = 1.0f, S = 0.0f;       // D_{-2}, D_{-1}, S_{-1}
    float sqim1 = 0.0f;                          // alpha[i-1]^2 (halo cut)
    float al  = sA[0];
    float sqi = al * al;

#define FSTEP(RC) do {                                   \
        float alp1 = sA[(RC) + 1];                       \
        float fv   = fS[(RC)];                           \
        float sq1  = alp1 * alp1;                        \
        float bi   = fmaf(al, sqi, 1.0f);                \
        float cim1 = fmaf(2.0f, al, sqi);                \
        float t    = (sqim1 * cim1) * Dmm;               \
        float Dn   = fmaf(bi, Dm, -t);                   \
        float Sn   = fmaf(-sqim1, S, fv * Dm);           \
        Dmm = Dm; Dm = Dn; S = Sn;                       \
        sqim1 = sqi; sqi = sq1; al = alp1;               \
    } while (0)

    #pragma unroll
    for (int rc = 0; rc < HF; ++rc) FSTEP(rc);           // left halo warmup

    for (int k = 0; k < NTILES; ++k) {                   // rolled (I$-friendly)
        // checkpoint (cp, dp) entering this tile (rcp off the chain)
        float r    = frcp(Dm);
        float cim1 = fmaf(2.0f, al, sqi);                // c_{base-1}
        ckS[k * TPB + tid]         = (cim1 * Dmm) * r;   // cp_in
        ckS[CKOFF + k * TPB + tid] = S * r;              // dp_in
        const int base = HF + (k << 4);
        #pragma unroll
        for (int j = 0; j < 16; ++j) FSTEP(base + j);
    }
#undef FSTEP

    // ======= phase 2: per tile (desc): recompute cp/dp, back-substitute ======
    float u = 0.0f;                                      // halo cut at top
    for (int k = NTILES - 1; k >= 0; --k) {              // rolled
        const int base = HF + (k << 4);
        const float cp_in = ckS[k * TPB + tid];
        const float dp_in = ckS[CKOFF + k * TPB + tid];

        float al2 = sA[base];
        float sq2 = al2 * al2;
        float alm = sA[base - 1];
        float sm1 = alm * alm;                           // a_base
        float cpl[16], dpl[16];
        float dmm, dm, sl, qim1, qi, a2;
        {   // j = 0: fold incoming (cp_in, dp_in); local D~_{-1} = 1
            float alp1 = sA[base + 1];
            float fv   = fS[base];
            float sq1  = alp1 * alp1;
            float bi   = fmaf(al2, sq2, 1.0f);
            float D0   = fmaf(-sm1, cp_in, bi);
            float S0   = fmaf(-sm1, dp_in, fv);
            float r    = frcp(D0);
            float cj   = fmaf(2.0f, alp1, sq1);
            cpl[0] = cj * r;
            dpl[0] = S0 * r;
            dmm = 1.0f; dm = D0; sl = S0;
            qim1 = sq2; qi = sq1; a2 = alp1;
        }
        #pragma unroll
        for (int j = 1; j < 16; ++j) {
            float alp1 = sA[base + j + 1];
            float fv   = fS[base + j];
            float sq1  = alp1 * alp1;
            float bi   = fmaf(a2, qi, 1.0f);
            float cim1 = fmaf(2.0f, a2, qi);
            float t    = (qim1 * cim1) * dmm;
            float dn   = fmaf(bi, dm, -t);
            float sn   = fmaf(-qim1, sl, fv * dm);
            float r    = frcp(dn);
            float cj   = fmaf(2.0f, alp1, sq1);
            cpl[j] = (cj * dm) * r;
            dpl[j] = sn * r;
            dmm = dm; dm = dn; sl = sn;
            qim1 = qi; qi = sq1; a2 = alp1;
        }
        #pragma unroll
        for (int j = 15; j >= 0; --j) {
            u = fmaf(-cpl[j], u, dpl[j]);
            dpl[j] = u;
        }
        if (k < 8) {                                     // owned tiles only
            float4* o4 = reinterpret_cast<float4*>(
                out + (size_t)(row0 + tid) * N_COLSK + s + (k << 4));
            o4[0] = make_float4(dpl[0],  dpl[1],  dpl[2],  dpl[3]);
            o4[1] = make_float4(dpl[4],  dpl[5],  dpl[6],  dpl[7]);
            o4[2] = make_float4(dpl[8],  dpl[9],  dpl[10], dpl[11]);
            o4[3] = make_float4(dpl[12], dpl[13], dpl[14], dpl[15]);
        }
    }
}

extern "C" void kernel_launch(void* const* d_in, const int* in_sizes, int n_in,
                              void* d_out, int out_size)
{
    const float* alpha = (const float*)d_in[0];
    const float* f     = (const float*)d_in[1];
    float* out         = (float*)d_out;

    static int smem_set = 0;
    if (!smem_set) {
        cudaFuncSetAttribute(thomas_chunk_kernel,
                             cudaFuncAttributeMaxDynamicSharedMemorySize,
                             SMEM_BYTES);
        smem_set = 1;
    }

    dim3 grid(N_COLSK / L_OWN, 2048 / TPB);              // (64, 32)
    thomas_chunk_kernel<<<grid, TPB, SMEM_BYTES>>>(alpha, f, out);
}

// round 15
// speedup vs baseline: 1.3090x; 1.3090x over previous
#include <cuda_runtime.h>
#include <cstdint>

// Batched Thomas tridiagonal solve, B=2048, N=8192, chunked via diagonal
// dominance (alpha in [0,0.3)). Continuant (D/S) recurrence, rcp.approx
// off the dependence chain.
// R14 = R12's proven 59us config (TPB=128, L=128, HF=8, HB=16, rolled tiles,
// smem checkpoints, occ-2) with VECTORIZED smem access: alpha + f read as
// LDS.128 quads (pitch 156 -> lane windows tile all 32 banks, conflict-free).
// LDS ops/thread ~600 -> ~205. R13 proved the kernel is L1/LDS-bound at the
// SM level (more warps made it slower, L1 60%), so cutting LDS ops is the lever.

#define N_COLSK 8192
#define L_OWN   128
#define HF      8
#define HB      16
#define SPAN_C  153                 // staged cols: HF + 128 + HB + 1
#define PITCH   156                 // row pitch (PITCH*4 B): l*28 mod 32 -> conflict-free LDS.128
#define TPB     128
#define NTILES  9                   // 9 x 16 steps over the 144 post-halo cols
#define TAIL_C  (SPAN_C - TPB)      // 25

#define SM_F    (TPB * PITCH)                       // f slice (16B aligned)
#define SM_CK   (SM_F + PITCH)                      // checkpoints (cp then dp)
#define CKOFF   (NTILES * TPB)
#define SM_DUMP (SM_CK + 2 * NTILES * TPB)          // dump slots for masked lanes
#define SMEM_FLOATS (SM_DUMP + TPB)
#define SMEM_BYTES  (SMEM_FLOATS * 4)               // 90,224 B -> 2 blocks/SM

__device__ __forceinline__ float frcp(float x) {
    float r; asm("rcp.approx.f32 %0, %1;" : "=f"(r) : "f"(x)); return r;
}

// cp.async 4B; src_sz = 0 zero-fills the destination (OOB handling).
__device__ __forceinline__ void cpa4(unsigned int saddr, const float* g, int src_sz) {
    asm volatile("cp.async.ca.shared.global [%0], [%1], 4, %2;"
                 :: "r"(saddr), "l"(g), "r"(src_sz));
}

__global__ __launch_bounds__(TPB, 2)
void thomas_chunk_kernel(const float* __restrict__ alpha,
                         const float* __restrict__ f,
                         float* __restrict__ out)
{
    extern __shared__ float smem[];
    float* fS  = smem + SM_F;
    float* ckS = smem + SM_CK;

    const int tid  = threadIdx.x;
    const int cc   = blockIdx.x;                 // chunk column (0..63)
    const int row0 = blockIdx.y * TPB;
    const int s    = cc * L_OWN;
    const int col0 = s - HF;                     // first staged col (>= -8)

    // ================= cp.async staging (pitch 156, 153 cols) ===============
    {
        const unsigned int smb  = (unsigned int)__cvta_generic_to_shared(smem);
        const unsigned int dump = smb + (unsigned int)(SM_DUMP + tid) * 4u;

        const int c1 = col0 + tid;                       // cols 0..127
        const int c2 = col0 + TPB + tid;                 // cols 128..152 (tid<25)
        const int sz1 = (c1 >= 0 && c1 < N_COLSK) ? 4 : 0;
        const bool l2 = (tid < TAIL_C);
        const int sz2 = (l2 && c2 < N_COLSK) ? 4 : 0;
        const int c1c = max(0, min(c1, N_COLSK - 1));
        const int c2c = min(c2, N_COLSK - 1);

        const float* g1 = alpha + (size_t)row0 * N_COLSK + c1c;
        const float* g2 = alpha + (size_t)row0 * N_COLSK + c2c;
        unsigned int s1 = smb + (unsigned int)tid * 4u;
        unsigned int s2 = l2 ? (smb + (unsigned int)(TPB + tid) * 4u) : dump;
        const unsigned int step2 = l2 ? (PITCH * 4u) : 0u;

        #pragma unroll 4
        for (int r = 0; r < TPB; ++r) {
            cpa4(s1, g1, sz1);
            cpa4(s2, g2, sz2);
            s1 += PITCH * 4u;
            s2 += step2;
            g1 += N_COLSK; g2 += N_COLSK;
        }
        // f slice (broadcast rhs)
        const unsigned int fsb = smb + SM_F * 4u;
        cpa4(fsb + (unsigned int)tid * 4u, f + c1c, sz1);
        cpa4(l2 ? (fsb + (unsigned int)(TPB + tid) * 4u) : dump, f + c2c, sz2);

        asm volatile("cp.async.commit_group;");
        asm volatile("cp.async.wait_group 0;");
    }
    __syncthreads();

    const float* sA = smem + tid * PITCH;

    // ================= phase 1: forward continuant sweep =================
    float Dmm = 0.0f, Dm = 1.0f, S = 0.0f;       // D_{-2}, D_{-1}, S_{-1}
    float sqim1 = 0.0f;                          // alpha[i-1]^2 (halo cut)
    float al  = sA[0];
    float sqi = al * al;

    // one recurrence step: alp1 = alpha[i+1], fv = f[i]
#define FSTEP(ALP1, FV) do {                             \
        float alp1 = (ALP1);                             \
        float sq1  = alp1 * alp1;                        \
        float bi   = fmaf(al, sqi, 1.0f);                \
        float cim1 = fmaf(2.0f, al, sqi);                \
        float t    = (sqim1 * cim1) * Dmm;               \
        float Dn   = fmaf(bi, Dm, -t);                   \
        float Sn   = fmaf(-sqim1, S, (FV) * Dm);         \
        Dmm = Dm; Dm = Dn; S = Sn;                       \
        sqim1 = sqi; sqi = sq1; al = alp1;               \
    } while (0)

#define LOADQ(A, FQ, BASE) do {                                              \
        const float4* aq = reinterpret_cast<const float4*>(sA + (BASE));     \
        float4 q0 = aq[0], q1 = aq[1], q2 = aq[2], q3 = aq[3];               \
        (A)[0]=q0.x;(A)[1]=q0.y;(A)[2]=q0.z;(A)[3]=q0.w;                     \
        (A)[4]=q1.x;(A)[5]=q1.y;(A)[6]=q1.z;(A)[7]=q1.w;                     \
        (A)[8]=q2.x;(A)[9]=q2.y;(A)[10]=q2.z;(A)[11]=q2.w;                   \
        (A)[12]=q3.x;(A)[13]=q3.y;(A)[14]=q3.z;(A)[15]=q3.w;                 \
        (A)[16] = sA[(BASE) + 16];                                           \
        const float4* fq4 = reinterpret_cast<const float4*>(fS + (BASE));    \
        float4 g0 = fq4[0], g1 = fq4[1], g2 = fq4[2], g3 = fq4[3];           \
        (FQ)[0]=g0.x;(FQ)[1]=g0.y;(FQ)[2]=g0.z;(FQ)[3]=g0.w;                 \
        (FQ)[4]=g1.x;(FQ)[5]=g1.y;(FQ)[6]=g1.z;(FQ)[7]=g1.w;                 \
        (FQ)[8]=g2.x;(FQ)[9]=g2.y;(FQ)[10]=g2.z;(FQ)[11]=g2.w;               \
        (FQ)[12]=g3.x;(FQ)[13]=g3.y;(FQ)[14]=g3.z;(FQ)[15]=g3.w;             \
    } while (0)

    {   // left halo warmup: 8 steps (scalar loads, one-off)
        #pragma unroll
        for (int rc = 0; rc < HF; ++rc) FSTEP(sA[rc + 1], fS[rc]);
    }

    for (int k = 0; k < NTILES; ++k) {                   // rolled (I$-friendly)
        // checkpoint (cp, dp) entering this tile (rcp off the chain)
        float r    = frcp(Dm);
        float cim1 = fmaf(2.0f, al, sqi);                // c_{base-1}
        ckS[k * TPB + tid]         = (cim1 * Dmm) * r;   // cp_in
        ckS[CKOFF + k * TPB + tid] = S * r;              // dp_in

        const int base = HF + (k << 4);                  // 16B aligned (8+16k)
        float A[17], FQ[16];
        LOADQ(A, FQ, base);
        #pragma unroll
        for (int j = 0; j < 16; ++j) FSTEP(A[j + 1], FQ[j]);
    }
#undef FSTEP

    // ======= phase 2: per tile (desc): recompute cp/dp, back-substitute ======
    float u = 0.0f;                                      // halo cut at top
    for (int k = NTILES - 1; k >= 0; --k) {              // rolled
        const int base = HF + (k << 4);
        const float cp_in = ckS[k * TPB + tid];
        const float dp_in = ckS[CKOFF + k * TPB + tid];

        float A[17], FQ[16];
        LOADQ(A, FQ, base);
        float alm = sA[base - 1];

        float sm1 = alm * alm;                           // a_base
        float cpl[16], dpl[16];
        float dmm, dm, sl, qim1, qi, a2;
        {   // j = 0: fold incoming (cp_in, dp_in); local D~_{-1} = 1
            float al2  = A[0];
            float sq2  = al2 * al2;
            float alp1 = A[1];
            float sq1  = alp1 * alp1;
            float bi   = fmaf(al2, sq2, 1.0f);
            float D0   = fmaf(-sm1, cp_in, bi);
            float S0   = fmaf(-sm1, dp_in, FQ[0]);
            float r    = frcp(D0);
            float cj   = fmaf(2.0f, alp1, sq1);
            cpl[0] = cj * r;
            dpl[0] = S0 * r;
            dmm = 1.0f; dm = D0; sl = S0;
            qim1 = sq2; qi = sq1; a2 = alp1;
        }
        #pragma unroll
        for (int j = 1; j < 16; ++j) {
            float alp1 = A[j + 1];
            float sq1  = alp1 * alp1;
            float bi   = fmaf(a2, qi, 1.0f);
            float cim1 = fmaf(2.0f, a2, qi);
            float t    = (qim1 * cim1) * dmm;
            float dn   = fmaf(bi, dm, -t);
            float sn   = fmaf(-qim1, sl, FQ[j] * dm);
            float r    = frcp(dn);
            float cj   = fmaf(2.0f, alp1, sq1);
            cpl[j] = (cj * dm) * r;
            dpl[j] = sn * r;
            dmm = dm; dm = dn; sl = sn;
            qim1 = qi; qi = sq1; a2 = alp1;
        }
        #pragma unroll
        for (int j = 15; j >= 0; --j) {
            u = fmaf(-cpl[j], u, dpl[j]);
            dpl[j] = u;
        }
        if (k < 8) {                                     // owned tiles only
            float4* o4 = reinterpret_cast<float4*>(
                out + (size_t)(row0 + tid) * N_COLSK + s + (k << 4));
            o4[0] = make_float4(dpl[0],  dpl[1],  dpl[2],  dpl[3]);
            o4[1] = make_float4(dpl[4],  dpl[5],  dpl[6],  dpl[7]);
            o4[2] = make_float4(dpl[8],  dpl[9],  dpl[10], dpl[11]);
            o4[3] = make_float4(dpl[12], dpl[13], dpl[14], dpl[15]);
        }
    }
#undef LOADQ
}

extern "C" void kernel_launch(void* const* d_in, const int* in_sizes, int n_in,
                              void* d_out, int out_size)
{
    const float* alpha = (const float*)d_in[0];
    const float* f     = (const float*)d_in[1];
    float* out         = (float*)d_out;

    static int smem_set = 0;
    if (!smem_set) {
        cudaFuncSetAttribute(thomas_chunk_kernel,
                             cudaFuncAttributeMaxDynamicSharedMemorySize,
                             SMEM_BYTES);
        smem_set = 1;
    }

    dim3 grid(N_COLSK / L_OWN, 2048 / TPB);              // (64, 16)
    thomas_chunk_kernel<<<grid, TPB, SMEM_BYTES>>>(alpha, f, out);
}